// round 3
// baseline (speedup 1.0000x reference)
#include <cuda_runtime.h>
#include <cstdint>

// out[t, v] = bias[v] + sum_{q=0..3} W[v][q] * cos(x[t])^(q+1)
// (closed form of the CNOT-permuted Ry product state; phase cancels in |psi|^2)
//
// No smem, no sync: each thread owns one output float4 per iteration and
// RECOMPUTES cos(x[t]) via a 5-FMA even polynomial (x in [0,1), err ~1e-9).
// Block chunk = NT*ITERS float4s, per-thread stride NT. NT % 10 == 0 and
// chunk % 10 == 0  =>  vv = tid % 10 is loop-invariant: coefficients live in
// registers, t advances by 32 per iteration (no division in the loop).
// Stores: warp writes 512 contiguous bytes (STG.128). Loads: x[t] is a
// 10-lane-broadcast LDG.32 (~1 sector/warp). Pure DRAM-streaming kernel.

#define NT    320
#define ITERS 8
#define CHUNK (NT * ITERS)   // 2560 float4 per block

#define PACK2(o, lo, hi) \
    asm("mov.b64 %0, {%1, %2};" : "=l"(o) : "f"(lo), "f"(hi))
#define FMA2(d, a, b, c) \
    asm("fma.rn.f32x2 %0, %1, %2, %3;" : "=l"(d) : "l"(a), "l"(b), "l"(c))
#define MUL2(d, a, b) \
    asm("mul.rn.f32x2 %0, %1, %2;" : "=l"(d) : "l"(a), "l"(b))

__global__ void __launch_bounds__(NT, 5)
qmodel_kernel(const float* __restrict__ x,
              const float* __restrict__ W,     // (40,4) row-major
              const float* __restrict__ bias,  // (40,)
              float4* __restrict__ out4,       // (SEQ*10,) float4
              int total4)                      // SEQ*10
{
    const int tid   = threadIdx.x;
    const int base  = blockIdx.x * CHUNK;      // float4 index, % 10 == 0
    const int vv    = tid % 10;
    const int lane_t = tid / 10;               // 0..31
    const int t0    = base / 10 + lane_t;      // first t for this thread

    // ---- packed coefficients for outputs v0..v0+3 (loop-invariant) ----
    const int v0 = vv * 4;
    const float4 w0 = ((const float4*)W)[v0 + 0];
    const float4 w1 = ((const float4*)W)[v0 + 1];
    const float4 w2 = ((const float4*)W)[v0 + 2];
    const float4 w3 = ((const float4*)W)[v0 + 3];
    const float4 bb = *(const float4*)(bias + v0);

    unsigned long long c0a, c0b, c1a, c1b, c2a, c2b, c3a, c3b, c4a, c4b;
    PACK2(c0a, bb.x, bb.y);  PACK2(c0b, bb.z, bb.w);
    PACK2(c1a, w0.x, w1.x);  PACK2(c1b, w2.x, w3.x);
    PACK2(c2a, w0.y, w1.y);  PACK2(c2b, w2.y, w3.y);
    PACK2(c3a, w0.z, w1.z);  PACK2(c3b, w2.z, w3.z);
    PACK2(c4a, w0.w, w1.w);  PACK2(c4b, w2.w, w3.w);

    const bool full = (base + CHUNK <= total4);

    #pragma unroll
    for (int i = 0; i < ITERS; ++i) {
        const int g = base + i * NT + tid;     // output float4 index
        if (full || g < total4) {
            const float xv = x[t0 + 32 * i];

            // cos(xv), even minimax-ish Taylor on [0,1): err < 3e-9
            const float y = xv * xv;
            float u = fmaf(y, -2.7557319e-07f,  2.4801587e-05f);
            u = fmaf(y, u, -1.3888889e-03f);
            u = fmaf(y, u,  4.1666667e-02f);
            u = fmaf(y, u, -5.0000000e-01f);
            u = fmaf(y, u,  1.0000000e+00f);

            unsigned long long pu, pu2, pu3, pu4;
            PACK2(pu, u, u);
            MUL2(pu2, pu,  pu);
            MUL2(pu3, pu2, pu);
            MUL2(pu4, pu2, pu2);

            unsigned long long r01, r23;
            FMA2(r01, c1a, pu,  c0a);
            FMA2(r23, c1b, pu,  c0b);
            FMA2(r01, c2a, pu2, r01);
            FMA2(r23, c2b, pu2, r23);
            FMA2(r01, c3a, pu3, r01);
            FMA2(r23, c3b, pu3, r23);
            FMA2(r01, c4a, pu4, r01);
            FMA2(r23, c4b, pu4, r23);

            ulonglong2 r = make_ulonglong2(r01, r23);
            *(ulonglong2*)(out4 + g) = r;
        }
    }
}

extern "C" void kernel_launch(void* const* d_in, const int* in_sizes, int n_in,
                              void* d_out, int out_size)
{
    const float* x    = (const float*)d_in[0];
    // d_in[1] = q_weights: unused (global phase cancels in |psi|^2)
    const float* W    = (const float*)d_in[2];
    const float* bias = (const float*)d_in[3];
    float4* out4      = (float4*)d_out;

    const int seq    = in_sizes[0];
    const int total4 = seq * 10;                    // output float4 count
    const int blocks = (total4 + CHUNK - 1) / CHUNK;
    qmodel_kernel<<<blocks, NT>>>(x, W, bias, out4, total4);
}

// round 4
// speedup vs baseline: 1.6937x; 1.6937x over previous
#include <cuda_runtime.h>
#include <cstdint>

// out[t, v] = bias[v] + sum_{q=0..3} W[v][q] * cos(x[t])^(q+1)
// (closed form of the CNOT-permuted Ry product state; phase cancels in |psi|^2)
//
// Streaming kernel: 168MB stores, 4MB loads. No smem, no sync.
// Thread owns fixed v-group vv=tid%10 (coeffs packed in regs as f32x2).
// All ITERS x-loads are front-batched (MLP=8), then 8 independent
// poly->store chains. Warp stores 512 contiguous bytes (STG.128, evict-first).

#define NT    320
#define ITERS 8
#define CHUNK (NT * ITERS)   // 2560 float4 per block; %10==0 so vv loop-invariant

#define PACK2(o, lo, hi) \
    asm("mov.b64 %0, {%1, %2};" : "=l"(o) : "f"(lo), "f"(hi))
#define FMA2(d, a, b, c) \
    asm("fma.rn.f32x2 %0, %1, %2, %3;" : "=l"(d) : "l"(a), "l"(b), "l"(c))
#define MUL2(d, a, b) \
    asm("mul.rn.f32x2 %0, %1, %2;" : "=l"(d) : "l"(a), "l"(b))

__device__ __forceinline__ void eval_store(
    float xv,
    unsigned long long c0a, unsigned long long c0b,
    unsigned long long c1a, unsigned long long c1b,
    unsigned long long c2a, unsigned long long c2b,
    unsigned long long c3a, unsigned long long c3b,
    unsigned long long c4a, unsigned long long c4b,
    float4* __restrict__ dst)
{
    // cos(xv) for xv in [0,1): even Taylor, rel err < 3e-9
    const float y = xv * xv;
    float u = fmaf(y, -2.7557319e-07f,  2.4801587e-05f);
    u = fmaf(y, u, -1.3888889e-03f);
    u = fmaf(y, u,  4.1666667e-02f);
    u = fmaf(y, u, -5.0000000e-01f);
    u = fmaf(y, u,  1.0000000e+00f);

    unsigned long long pu, pu2, pu3, pu4;
    PACK2(pu, u, u);
    MUL2(pu2, pu,  pu);
    MUL2(pu3, pu2, pu);
    MUL2(pu4, pu2, pu2);

    unsigned long long r01, r23;
    FMA2(r01, c1a, pu,  c0a);
    FMA2(r23, c1b, pu,  c0b);
    FMA2(r01, c2a, pu2, r01);
    FMA2(r23, c2b, pu2, r23);
    FMA2(r01, c3a, pu3, r01);
    FMA2(r23, c3b, pu3, r23);
    FMA2(r01, c4a, pu4, r01);
    FMA2(r23, c4b, pu4, r23);

    // evict-first streaming store (write-once data)
    float2 lo = *(float2*)&r01;
    float2 hi = *(float2*)&r23;
    float4 r = make_float4(lo.x, lo.y, hi.x, hi.y);
    __stcs(dst, r);
}

__global__ void __launch_bounds__(NT)
qmodel_kernel(const float* __restrict__ x,
              const float* __restrict__ W,     // (40,4) row-major
              const float* __restrict__ bias,  // (40,)
              float4* __restrict__ out4,       // (SEQ*10,) float4
              int total4)                      // SEQ*10
{
    const int tid  = threadIdx.x;
    const int base = blockIdx.x * CHUNK;       // float4 index, % 10 == 0
    const int vv   = tid % 10;
    const int t0   = base / 10 + tid / 10;     // first t for this thread

    // ---- packed coefficients for outputs v0..v0+3 (loop-invariant) ----
    const int v0 = vv * 4;
    const float4 w0 = ((const float4*)W)[v0 + 0];
    const float4 w1 = ((const float4*)W)[v0 + 1];
    const float4 w2 = ((const float4*)W)[v0 + 2];
    const float4 w3 = ((const float4*)W)[v0 + 3];
    const float4 bb = *(const float4*)(bias + v0);

    unsigned long long c0a, c0b, c1a, c1b, c2a, c2b, c3a, c3b, c4a, c4b;
    PACK2(c0a, bb.x, bb.y);  PACK2(c0b, bb.z, bb.w);
    PACK2(c1a, w0.x, w1.x);  PACK2(c1b, w2.x, w3.x);
    PACK2(c2a, w0.y, w1.y);  PACK2(c2b, w2.y, w3.y);
    PACK2(c3a, w0.z, w1.z);  PACK2(c3b, w2.z, w3.z);
    PACK2(c4a, w0.w, w1.w);  PACK2(c4b, w2.w, w3.w);

    if (base + CHUNK <= total4) {
        // hot path: front-batch ALL loads (MLP = ITERS), then independent chains
        float xv[ITERS];
        #pragma unroll
        for (int i = 0; i < ITERS; ++i)
            xv[i] = x[t0 + 32 * i];

        #pragma unroll
        for (int i = 0; i < ITERS; ++i)
            eval_store(xv[i], c0a,c0b,c1a,c1b,c2a,c2b,c3a,c3b,c4a,c4b,
                       out4 + base + i * NT + tid);
    } else {
        #pragma unroll
        for (int i = 0; i < ITERS; ++i) {
            const int g = base + i * NT + tid;
            if (g < total4)
                eval_store(x[t0 + 32 * i], c0a,c0b,c1a,c1b,c2a,c2b,c3a,c3b,c4a,c4b,
                           out4 + g);
        }
    }
}

extern "C" void kernel_launch(void* const* d_in, const int* in_sizes, int n_in,
                              void* d_out, int out_size)
{
    const float* x    = (const float*)d_in[0];
    // d_in[1] = q_weights: unused (global phase cancels in |psi|^2)
    const float* W    = (const float*)d_in[2];
    const float* bias = (const float*)d_in[3];
    float4* out4      = (float4*)d_out;

    const int seq    = in_sizes[0];
    const int total4 = seq * 10;
    const int blocks = (total4 + CHUNK - 1) / CHUNK;
    qmodel_kernel<<<blocks, NT>>>(x, W, bias, out4, total4);
}